// round 17
// baseline (speedup 1.0000x reference)
#include <cuda_runtime.h>
#include <cuda_fp16.h>
#include <float.h>
#include <stdint.h>

#define B_   16
#define C_   64
#define H_   256
#define W_   256
#define OC_  128
#define OH_  254
#define OW_  254

#define TW   16      // tile width (px)
#define TH   16      // tile height (px) -> M = 256
#define PW   18      // patch width incl. halo
#define PH   18      // patch height incl. halo
#define TB   512     // 16 warps
#define GRID 152     // persistent, 1 CTA/SM
#define NT   (B_ * 16 * 16)   // 4096 tiles

#define XP   260     // padded NHWC extent (halo zeroed)

// patch smem: [y][x][ic] fp16, 128B per (y,x), bank-conflict-free via XOR swizzle
#define ROWB       128
#define YSTRIDE    (PW * ROWB)             // 2304
#define PATCH_SZ   (PH * YSTRIDE)          // 41472
#define SM_RED     0                       // 8 wm * 2 mt * 2 rh * 8 r * 4B = 1024
#define SM_PATCH   2048
#define SM_B       (SM_PATCH + 2 * PATCH_SZ)   // 84992
#define B_BYTES    147456                  // 9*4*16*32 fragments * 8B
#define SMEM_TOTAL (SM_B + B_BYTES)        // 232448 == 227 KB max dynamic smem

// fp16 NHWC padded input: [b][y][x][ic]
__device__ __align__(16) __half g_xh[(size_t)B_ * XP * XP * C_];   // 138 MB

// weights fp16, per-lane fragment order: [pos][kc(4)][nt(16)][lane(32)][4]
#define W_FRAGS (9 * 4 * 16 * 32)
__device__ __align__(16) __half g_wfrag[W_FRAGS * 4];

// exact-halo zero: region A x in [256,260) all y; region B y in [256,260), x<256
#define HALO_PER_B 2064
__global__ void zero_halo_kernel() {
    int t = blockIdx.x * blockDim.x + threadIdx.x;
    if (t >= B_ * HALO_PER_B) return;
    int b = t / HALO_PER_B;
    int r = t - b * HALO_PER_B;
    int y, x;
    if (r < 1040) { y = r >> 2;          x = 256 + (r & 3); }
    else { r -= 1040; y = 256 + (r >> 8); x = r & 255; }
    uint4 z = make_uint4(0, 0, 0, 0);
    uint4* p = (uint4*)(g_xh + ((((size_t)b * XP) + y) * XP + x) * C_);
    #pragma unroll
    for (int i = 0; i < 8; i++) p[i] = z;
}

__global__ __launch_bounds__(256)
void transpose_kernel(const float* __restrict__ x) {
    __shared__ __half s[64 * 72];
    const int x0 = blockIdx.x * 64;
    const int y  = blockIdx.y;
    const int b  = blockIdx.z;
    const int tid = threadIdx.x;
    #pragma unroll
    for (int k = 0; k < 16; k++) {
        int idx = tid + k * 256;
        int ic = idx >> 6;
        int xo = idx & 63;
        float v = __ldg(x + (((size_t)b * C_ + ic) * H_ + y) * W_ + x0 + xo);
        s[xo * 72 + ic] = __float2half(v);
    }
    __syncthreads();
    #pragma unroll
    for (int k = 0; k < 2; k++) {
        int idx = tid + k * 256;
        int px = idx >> 3;
        int q  = idx & 7;
        uint4 v = *(const uint4*)(s + px * 72 + q * 8);
        *(uint4*)(g_xh + ((((size_t)b * XP) + y) * XP + x0 + px) * C_ + q * 8) = v;
    }
}

__global__ void prep_weights_kernel(const float* __restrict__ w) {
    int i = blockIdx.x * blockDim.x + threadIdx.x;
    if (i >= W_FRAGS) return;
    int lane = i & 31;
    int nt   = (i >> 5) & 15;
    int kc   = (i >> 9) & 3;
    int pos  = i >> 11;
    int oc   = nt * 8 + (lane >> 2);
    int kk0  = (lane & 3) * 2;
    int ics[4] = { kc*16 + kk0, kc*16 + kk0 + 1, kc*16 + kk0 + 8, kc*16 + kk0 + 9 };
    __half outv[4];
    #pragma unroll
    for (int j = 0; j < 4; j++)
        outv[j] = __float2half(w[((size_t)oc * C_ + ics[j]) * 9 + pos]);
    *(uint2*)(&g_wfrag[(size_t)i * 4]) = *(uint2*)outv;
}

__device__ __forceinline__ void mma16816(float* d, const uint32_t* a, const uint32_t* b) {
    asm volatile(
        "mma.sync.aligned.m16n8k16.row.col.f32.f16.f16.f32 "
        "{%0,%1,%2,%3},{%4,%5,%6,%7},{%8,%9},{%0,%1,%2,%3};"
        : "+f"(d[0]), "+f"(d[1]), "+f"(d[2]), "+f"(d[3])
        : "r"(a[0]), "r"(a[1]), "r"(a[2]), "r"(a[3]), "r"(b[0]), "r"(b[1]));
}
__device__ __forceinline__ void ldmx4(uint32_t* r, uint32_t addr) {
    asm volatile("ldmatrix.sync.aligned.m8n8.x4.shared.b16 {%0,%1,%2,%3},[%4];"
                 : "=r"(r[0]), "=r"(r[1]), "=r"(r[2]), "=r"(r[3]) : "r"(addr));
}
__device__ __forceinline__ void cp16(uint32_t dst, const void* src) {
    asm volatile("cp.async.cg.shared.global [%0], [%1], 16;" :: "r"(dst), "l"(src));
}

__global__ __launch_bounds__(TB, 1)
void conv_mma_min_kernel(const float* __restrict__ bias,
                         float* __restrict__ out)
{
    extern __shared__ __align__(128) char smem[];
    const uint32_t sb = (uint32_t)__cvta_generic_to_shared(smem);
    const int tid  = threadIdx.x;
    const int lane = tid & 31;
    const int warp = tid >> 5;
    const int wm   = warp >> 1;           // 0..7 : M slice (32 px)
    const int wn   = warp & 1;            // 0..1 : N half (64 oc)

    // ---- one-time: weights into smem (fragment-ordered, straight copy) ----
    for (int j = tid; j < B_BYTES / 16; j += TB)
        cp16(sb + SM_B + j * 16, (const char*)g_wfrag + (size_t)j * 16);

    // ---- async patch stage from NHWC fp16 (2592 x 16B granules, swizzled) ----
    auto stage = [&](int t, int buf) {
        const int bt  = t >> 8;
        const int rem = t & 255;
        const int gy0 = (rem >> 4) * TH;
        const int gx0 = (rem & 15) * TW;
        const __half* base = g_xh + (((size_t)bt * XP + gy0) * XP + gx0) * C_;
        const uint32_t db = sb + SM_PATCH + buf * PATCH_SZ;
        #pragma unroll
        for (int k = 0; k < 6; k++) {
            int g = tid + k * TB;
            if (g < PH * PW * 8) {
                int y  = g / (PW * 8);
                int r2 = g - y * (PW * 8);
                int xx = r2 >> 3;
                int i  = r2 & 7;
                cp16(db + y * YSTRIDE + xx * ROWB + ((i * 16) ^ ((xx & 7) * 16)),
                     base + ((size_t)y * XP + xx) * C_ + i * 8);
            }
        }
    };

    const int arow = 2 * wm;
    const int acol = lane & 15;
    const uint32_t chunk16 = (uint32_t)(lane >> 4) * 16;
    const int q = lane & 3;
    const int r = lane >> 2;

    float bpair[8][2];
    #pragma unroll
    for (int nt = 0; nt < 8; nt++) {
        int c0 = wn * 64 + nt * 8 + q * 2;
        bpair[nt][0] = __ldg(bias + c0);
        bpair[nt][1] = __ldg(bias + c0 + 1);
    }

    int buf = 0;
    stage(blockIdx.x, 0);
    asm volatile("cp.async.commit_group;");

    for (int t = blockIdx.x; t < NT; t += GRID) {
        asm volatile("cp.async.wait_group 0;");
        __syncthreads();                      // patch[buf] (+B first iter) visible; RED reusable
        if (t + GRID < NT) {
            stage(t + GRID, buf ^ 1);         // overlaps MMA below
            asm volatile("cp.async.commit_group;");
        }

        float d[2][8][4];
        #pragma unroll
        for (int mt = 0; mt < 2; mt++)
            #pragma unroll
            for (int nt = 0; nt < 8; nt++)
                #pragma unroll
                for (int j = 0; j < 4; j++) d[mt][nt][j] = 0.f;

        const uint32_t pbase = sb + SM_PATCH + buf * PATCH_SZ;

        #pragma unroll 1
        for (int c = 0; c < 9; ++c) {
            const int ky = c / 3, kx = c - 3 * ky;
            const int xl = acol + kx;
            const uint32_t s7 = (uint32_t)(xl & 7) * 16;
            const uint32_t rowbase = pbase + (uint32_t)(arow + ky) * YSTRIDE
                                   + (uint32_t)xl * ROWB;
            const char* bsm = smem + SM_B + ((size_t)(c * 4) * 16 + wn * 8) * 256 + lane * 8;

            #pragma unroll
            for (int kc = 0; kc < 4; kc++) {
                uint32_t aoff = (chunk16 + (uint32_t)kc * 32) ^ s7;
                uint32_t ah0[4], ah1[4];
                ldmx4(ah0, rowbase + aoff);
                ldmx4(ah1, rowbase + YSTRIDE + aoff);
                const char* bk = bsm + (size_t)kc * 4096;   // 16 nt * 256B
                uint2 bf[8];
                #pragma unroll
                for (int nt = 0; nt < 8; nt++)
                    bf[nt] = *(const uint2*)(bk + nt * 256);
                #pragma unroll
                for (int nt = 0; nt < 8; nt++) {
                    mma16816(d[0][nt], ah0, (const uint32_t*)&bf[nt]);
                    mma16816(d[1][nt], ah1, (const uint32_t*)&bf[nt]);
                }
            }
        }

        // ---- epilogue: min over 128 oc (+bias), pairwise via named barrier ----
        float mv[2][2];
        #pragma unroll
        for (int mt = 0; mt < 2; mt++) {
            #pragma unroll
            for (int rh = 0; rh < 2; rh++) {
                float m = FLT_MAX;
                #pragma unroll
                for (int nt = 0; nt < 8; nt++) {
                    m = fminf(m, d[mt][nt][2 * rh]     + bpair[nt][0]);
                    m = fminf(m, d[mt][nt][2 * rh + 1] + bpair[nt][1]);
                }
                m = fminf(m, __shfl_xor_sync(0xffffffffu, m, 1));
                m = fminf(m, __shfl_xor_sync(0xffffffffu, m, 2));
                mv[mt][rh] = m;               // valid on q==0 lanes
            }
        }
        float* red = (float*)(smem + SM_RED) + wm * 32;   // [mt][rh][r]
        if (wn == 1 && q == 0) {
            #pragma unroll
            for (int mt = 0; mt < 2; mt++)
                #pragma unroll
                for (int rh = 0; rh < 2; rh++)
                    red[(mt * 2 + rh) * 8 + r] = mv[mt][rh];
        }
        asm volatile("bar.sync %0, 64;" :: "r"(1 + wm) : "memory");
        if (wn == 0 && q == 0) {
            const int bt  = t >> 8;
            const int rem = t & 255;
            const int gy0 = (rem >> 4) * TH;
            const int gx0 = (rem & 15) * TW;
            float* ob = out + (size_t)bt * OH_ * OW_;
            #pragma unroll
            for (int mt = 0; mt < 2; mt++) {
                int oy = gy0 + 2 * wm + mt;
                if (oy >= OH_) continue;
                #pragma unroll
                for (int rh = 0; rh < 2; rh++) {
                    int ox = gx0 + r + 8 * rh;
                    if (ox >= OW_) continue;
                    float m = fminf(mv[mt][rh], red[(mt * 2 + rh) * 8 + r]);
                    ob[(size_t)oy * OW_ + ox] = 2.0f * m;
                }
            }
        }
        buf ^= 1;
        // next-iter top __syncthreads orders RED reuse
    }
}

extern "C" void kernel_launch(void* const* d_in, const int* in_sizes, int n_in,
                              void* d_out, int out_size)
{
    const float* x    = (const float*)d_in[0];   // (16,64,256,256)
    const float* w    = (const float*)d_in[1];   // (128,64,3,3)
    const float* bias = (const float*)d_in[2];   // (128,)
    float* out = (float*)d_out;                  // (16,1,254,254)

    cudaFuncSetAttribute(conv_mma_min_kernel,
                         cudaFuncAttributeMaxDynamicSharedMemorySize, SMEM_TOTAL);

    zero_halo_kernel<<<(B_ * HALO_PER_B + 255) / 256, 256>>>();
    {
        dim3 tg(4, 256, B_);
        transpose_kernel<<<tg, 256>>>(x);
    }
    prep_weights_kernel<<<(W_FRAGS + 255) / 256, 256>>>(w);

    conv_mma_min_kernel<<<GRID, TB, SMEM_TOTAL>>>(bias, out);
    (void)in_sizes; (void)n_in; (void)out_size;
}